// round 11
// baseline (speedup 1.0000x reference)
#include <cuda_runtime.h>
#include <math.h>

#define WW 512
#define HH 512
#define NIMG 8
#define HWSZ (HH * WW)
#define NPLANES 16            // 2 streams (p, target) x 8 samples
#define TOTALSZ (NPLANES * HWSZ)
#define NITER 50

#define STRIPS 5              // 5 strips x 120 output cols (lanes 1..30 of 32x float4)
#define CHUNK_ROWS 16
#define CHUNKS 32             // 512 / 16
#define WARPS_TOTAL (STRIPS * CHUNKS * NPLANES)   // 2560

// open-init sweep config
#define SWEEP_BLOCK 256
#define SWEEP_GRID (WARPS_TOTAL / (SWEEP_BLOCK / 32))  // 320

// fused-2 iteration kernel config
#define IT2_BLOCK 128
#define IT2_GRID (WARPS_TOTAL / (IT2_BLOCK / 32))      // 640

// Static scratch (no allocations allowed in kernel_launch)
__device__ float g_p[NIMG * HWSZ];     // sigmoid(output), kept for final reduction
__device__ float g_imgA[TOTALSZ];      // ping
__device__ float g_imgB[TOTALSZ];      // pong
__device__ float g_skel[TOTALSZ];      // skeleton accumulators (both streams)
__device__ double g_sums[NIMG][7];     // per-sample reduction accumulators

// ---------------------------------------------------------------------------
// float4 helpers
// ---------------------------------------------------------------------------
__device__ __forceinline__ float4 f44(float v) { return make_float4(v, v, v, v); }
__device__ __forceinline__ float4 min4(float4 a, float4 b) {
    return make_float4(fminf(a.x, b.x), fminf(a.y, b.y), fminf(a.z, b.z), fminf(a.w, b.w));
}
__device__ __forceinline__ float4 max4(float4 a, float4 b) {
    return make_float4(fmaxf(a.x, b.x), fmaxf(a.y, b.y), fmaxf(a.z, b.z), fmaxf(a.w, b.w));
}
__device__ __forceinline__ float4 vmin3(float4 a, float4 b, float4 c) { return min4(min4(a, b), c); }
__device__ __forceinline__ float4 vmax3(float4 a, float4 b, float4 c) { return max4(max4(a, b), c); }
// horizontal 3-tap combine from PRE-SHUFFLED edges (L = left lane's .w, R = right lane's .x)
__device__ __forceinline__ float4 comb_min(float4 v, float L, float R, int lane) {
    if (lane == 0)  L = INFINITY;
    if (lane == 31) R = INFINITY;
    float m01 = fminf(v.x, v.y), m23 = fminf(v.z, v.w);
    return make_float4(fminf(L, m01), fminf(m01, v.z), fminf(v.y, m23), fminf(m23, R));
}
__device__ __forceinline__ float4 comb_max(float4 v, float L, float R, int lane) {
    if (lane == 0)  L = -INFINITY;
    if (lane == 31) R = -INFINITY;
    float m01 = fmaxf(v.x, v.y), m23 = fmaxf(v.z, v.w);
    return make_float4(fmaxf(L, m01), fmaxf(m01, v.z), fmaxf(v.y, m23), fmaxf(m23, R));
}
// same-step variants (open-init only)
__device__ __forceinline__ float4 hmin3(float4 v, int lane) {
    float L = __shfl_up_sync(0xffffffffu, v.w, 1);
    float R = __shfl_down_sync(0xffffffffu, v.x, 1);
    return comb_min(v, L, R, lane);
}
__device__ __forceinline__ float4 hmax3(float4 v, int lane) {
    float L = __shfl_up_sync(0xffffffffu, v.w, 1);
    float R = __shfl_down_sync(0xffffffffu, v.x, 1);
    return comb_max(v, L, R, lane);
}
__device__ __forceinline__ float4 relu_sub(float4 a, float4 b) {
    return make_float4(fmaxf(0.0f, a.x - b.x), fmaxf(0.0f, a.y - b.y),
                       fmaxf(0.0f, a.z - b.z), fmaxf(0.0f, a.w - b.w));
}
__device__ __forceinline__ void skel_upd(float4& s, float4 d) {
    s.x += fmaxf(0.0f, fmaf(-s.x, d.x, d.x));
    s.y += fmaxf(0.0f, fmaf(-s.y, d.y, d.y));
    s.z += fmaxf(0.0f, fmaf(-s.z, d.z, d.z));
    s.w += fmaxf(0.0f, fmaf(-s.w, d.w, d.w));
}

// ---------------------------------------------------------------------------
// Init: p = sigmoid(output); imgA[stream0] = p, imgA[stream1] = target
// ---------------------------------------------------------------------------
__global__ void k_init(const float4* __restrict__ out, const float4* __restrict__ tgt) {
    int i = blockIdx.x * blockDim.x + threadIdx.x;
    int stride = gridDim.x * blockDim.x;
    float4* gp = (float4*)g_p;
    float4* ga = (float4*)g_imgA;
    float4* gb = (float4*)(g_imgA + NIMG * HWSZ);
    const int n4 = NIMG * HWSZ / 4;
    for (; i < n4; i += stride) {
        float4 o = out[i];
        float4 v;
        v.x = 1.0f / (1.0f + expf(-o.x));
        v.y = 1.0f / (1.0f + expf(-o.y));
        v.z = 1.0f / (1.0f + expf(-o.z));
        v.w = 1.0f / (1.0f + expf(-o.w));
        gp[i] = v;
        ga[i] = v;
        gb[i] = tgt[i];
    }
}

// ---------------------------------------------------------------------------
// Warp-sweep open-init:  skel = relu(img - dilate(erode(img)))
// ---------------------------------------------------------------------------
__global__ void __launch_bounds__(SWEEP_BLOCK, 3) k_open_init() {
    const int lane = threadIdx.x & 31;
    const int gw = (blockIdx.x * SWEEP_BLOCK + threadIdx.x) >> 5;
    const int strip = gw % STRIPS;
    const int t = gw / STRIPS;
    const int chunk = t & (CHUNKS - 1);
    const int z = t >> 5;

    const float* __restrict__ src = g_imgA + z * HWSZ;
    float* __restrict__ skel = g_skel + z * HWSZ;

    const int c0 = strip * 120 - 4 + 4 * lane;
    const bool colok = (c0 >= 0) && (c0 < WW);
    const bool stok = (lane >= 1) && (lane <= 30) && (c0 < WW);
    const int r0 = chunk * CHUNK_ROWS;
    const int ylim = r0 + 2;

    int y = r0 - 2;
    const float* srcp = src + y * WW + c0;
    float* const skb = skel + c0;

    float4 ia = f44(INFINITY), ib = f44(INFINITY), ic;
    float4 ha = f44(-INFINITY), hb = f44(-INFINITY), hc;

#define OPEN_STEP(IA, IB, IC, HA, HB, HC)                                      \
    {                                                                          \
        bool ldok = colok && ((unsigned)y < (unsigned)HH);                     \
        IC = ldok ? *(const float4*)srcp : f44(INFINITY);                      \
        float4 e1_ = min4(vmin3(IA, IB, IC), hmin3(IB, lane));                 \
        if (!colok || (unsigned)(y - 1) >= (unsigned)HH) e1_ = f44(-INFINITY); \
        HC = hmax3(e1_, lane);                                                 \
        if (y >= ylim) {                                                       \
            float4 d_ = vmax3(HA, HB, HC);                                     \
            if (stok) {                                                        \
                float4 o_ = relu_sub(IA, d_);                                  \
                *(float4*)(skb + (y - 2) * WW) = o_;                           \
            }                                                                  \
        }                                                                      \
        ++y;                                                                   \
        srcp += WW;                                                            \
    }

#pragma unroll 1
    for (int k = 0; k < 6; ++k) {
        OPEN_STEP(ia, ib, ic, ha, hb, hc);
        OPEN_STEP(ib, ic, ia, hb, hc, ha);
        OPEN_STEP(ic, ia, ib, hc, ha, hb);
    }
    OPEN_STEP(ia, ib, ic, ha, hb, hc);
    OPEN_STEP(ib, ic, ia, hb, hc, ha);
#undef OPEN_STEP
}

// ---------------------------------------------------------------------------
// Fused TWO skeleton iterations, software-pipelined shuffles.
// At the step that consumes img row y (y = r0 + s - 4, s = 0..24):
//   E1[y-1] = min(minI2, I[y], hminI(I[y-1]))   [edges shuffled last step]
//   E2[y-2] = F row, same pattern
//   H[y-3]  = hmax(mask(F[y-3]))                [F edges shuffled last step]
//   E3[y-3] = erode(F)                           (same F edges as hmin)
//   B[y-4]  = hmax(mask(E3[y-4]))               [edges shuffled last step]
//   s>=8  : D1[y-4]=max(maxH2,H[y-3]); delta1 = relu(E1[y-4]-D1); prefetch skel
//   s>=9  : D2[y-5]=max(maxB2,B[y-4]); delta2 = relu(E2[y-5]-D2);
//           skel[y-5] += both deltas; img[y-5] = E2[y-5]
// Pairwise min2/max2 windows are EXACT (no junk smear from fill steps).
// ---------------------------------------------------------------------------
template<bool IN>
__device__ __forceinline__ void it2_body(
    const float* __restrict__ src, float* __restrict__ dst,
    float* __restrict__ skel, const int lane, const int c0, const int r0)
{
    const bool colok = IN || ((c0 >= 0) && (c0 < WW));
    const bool stok = (lane >= 1) && (lane <= 30) && (IN || (c0 < WW));

    const float* srcp = src + (r0 - 4) * WW + c0;
    float* const skb = skel + c0;
    float* const dsb = dst + c0;

    int y = r0 - 4;
    float4 pf;
    {
        bool ldok = colok && (IN || (unsigned)y < (unsigned)HH);
        pf = ldok ? *(const float4*)srcp : f44(INFINITY);
        srcp += WW;
    }

    float4 iPrev = f44(INFINITY), minI2 = f44(INFINITY);
    float  iL = INFINITY, iR = INFINITY;
    float4 ePrev = f44(INFINITY), minE2 = f44(INFINITY);
    float4 eK2 = f44(INFINITY), eK3 = f44(INFINITY);
    float  eL = INFINITY, eR = INFINITY;
    float4 fPrev = f44(INFINITY), minF2 = f44(INFINITY);
    float4 fK2 = f44(INFINITY), fK3 = f44(INFINITY);
    float  fL = INFINITY, fR = INFINITY;
    float  fLm = -INFINITY, fRm = -INFINITY;    // masked F edges (boundary only)
    float4 e3Prev = f44(-INFINITY);             // col-masked E3 row
    float  bL = -INFINITY, bR = -INFINITY;
    float4 HPrev = f44(-INFINITY), maxH2 = f44(-INFINITY);
    float4 BPrev = f44(-INFINITY), maxB2 = f44(-INFINITY);
    float4 dprev = f44(0.0f), spf = f44(0.0f);

#define STEPX(DO_D1, DO_OUT)                                                   \
    {                                                                          \
        float4 icur = pf;                                                      \
        {                                                                      \
            bool ldok = colok && (IN || (unsigned)(y + 1) < (unsigned)HH);     \
            pf = ldok ? *(const float4*)srcp : f44(INFINITY);                  \
            srcp += WW;                                                        \
        }                                                                      \
        /* E1[y-1] */                                                          \
        float4 eNew = min4(min4(minI2, icur), comb_min(iPrev, iL, iR, lane));  \
        iL = __shfl_up_sync(0xffffffffu, icur.w, 1);                           \
        iR = __shfl_down_sync(0xffffffffu, icur.x, 1);                         \
        minI2 = min4(iPrev, icur);                                             \
        iPrev = icur;                                                          \
        /* E2[y-2] */                                                          \
        float4 fNew = min4(min4(minE2, eNew), comb_min(ePrev, eL, eR, lane));  \
        eL = __shfl_up_sync(0xffffffffu, eNew.w, 1);                           \
        eR = __shfl_down_sync(0xffffffffu, eNew.x, 1);                         \
        minE2 = min4(ePrev, eNew);                                             \
        /* H[y-3] = hmax(mask(F[y-3])) */                                      \
        float4 HNew;                                                           \
        if (IN) {                                                              \
            HNew = comb_max(fPrev, fL, fR, lane);                              \
        } else {                                                               \
            float4 vm = colok ? fPrev : f44(-INFINITY);                        \
            HNew = ((unsigned)(y - 3) < (unsigned)HH)                          \
                       ? comb_max(vm, fLm, fRm, lane) : f44(-INFINITY);        \
        }                                                                      \
        /* E3[y-3] */                                                          \
        float4 e3New = min4(min4(minF2, fNew), comb_min(fPrev, fL, fR, lane)); \
        fL = __shfl_up_sync(0xffffffffu, fNew.w, 1);                           \
        fR = __shfl_down_sync(0xffffffffu, fNew.x, 1);                         \
        if (!IN) {                                                             \
            float4 fm = colok ? fNew : f44(-INFINITY);                         \
            fLm = __shfl_up_sync(0xffffffffu, fm.w, 1);                        \
            fRm = __shfl_down_sync(0xffffffffu, fm.x, 1);                      \
        }                                                                      \
        minF2 = min4(fPrev, fNew);                                             \
        /* B[y-4] = hmax(mask(E3[y-4])) */                                     \
        float4 BNew;                                                           \
        if (IN) {                                                              \
            BNew = comb_max(e3Prev, bL, bR, lane);                             \
        } else {                                                               \
            BNew = ((unsigned)(y - 4) < (unsigned)HH)                          \
                       ? comb_max(e3Prev, bL, bR, lane) : f44(-INFINITY);      \
        }                                                                      \
        float4 e3m = (IN || colok) ? e3New : f44(-INFINITY);                   \
        bL = __shfl_up_sync(0xffffffffu, e3m.w, 1);                            \
        bR = __shfl_down_sync(0xffffffffu, e3m.x, 1);                          \
        /* output row y-5 (uses dprev/spf from previous step) */               \
        if (DO_OUT) {                                                          \
            float4 D2 = max4(maxB2, BNew);                                     \
            if (stok) {                                                        \
                float4 d2 = relu_sub(fK3, D2);                                 \
                float4 s4 = spf;                                               \
                skel_upd(s4, dprev);                                           \
                skel_upd(s4, d2);                                              \
                *(float4*)(skb + (y - 5) * WW) = s4;                           \
                *(float4*)(dsb + (y - 5) * WW) = fK3;                          \
            }                                                                  \
        }                                                                      \
        /* delta1 for row y-4 + skel prefetch (consumed next step) */          \
        if (DO_D1) {                                                           \
            float4 D1 = max4(maxH2, HNew);                                     \
            dprev = relu_sub(eK3, D1);                                         \
            if (stok) spf = *(const float4*)(skb + (y - 4) * WW);              \
        }                                                                      \
        /* state shifts (exact pairwise windows + 3-step delay chains) */      \
        maxH2 = max4(HPrev, HNew); HPrev = HNew;                               \
        maxB2 = max4(BPrev, BNew); BPrev = BNew;                               \
        eK3 = eK2; eK2 = ePrev; ePrev = eNew;                                  \
        fK3 = fK2; fK2 = fPrev; fPrev = fNew;                                  \
        e3Prev = e3m;                                                          \
        ++y;                                                                   \
    }

    // fill: s = 0..7
#pragma unroll 2
    for (int s = 0; s < 8; ++s) STEPX(false, false)
    // s = 8: first delta1
    STEPX(true, false)
    // steady: s = 9..23
#pragma unroll 3
    for (int s = 9; s < 24; ++s) STEPX(true, true)
    // s = 24: last output (no further delta1 needed)
    STEPX(false, true)
#undef STEPX
}

__global__ void __launch_bounds__(IT2_BLOCK, 4) k_iter2(int flip) {
    const int lane = threadIdx.x & 31;
    const int gw = (blockIdx.x * IT2_BLOCK + threadIdx.x) >> 5;
    const int strip = gw % STRIPS;
    const int t = gw / STRIPS;
    const int chunk = t & (CHUNKS - 1);
    const int z = t >> 5;

    const float* __restrict__ src = (flip ? g_imgB : g_imgA) + z * HWSZ;
    float* __restrict__ dst = (flip ? g_imgA : g_imgB) + z * HWSZ;
    float* __restrict__ skel = g_skel + z * HWSZ;

    const int c0 = strip * 120 - 4 + 4 * lane;
    const int r0 = chunk * CHUNK_ROWS;

    const bool interior = (chunk >= 1) && (chunk <= 30) &&
                          (strip >= 1) && (strip <= 3);
    if (interior)
        it2_body<true>(src, dst, skel, lane, c0, r0);
    else
        it2_body<false>(src, dst, skel, lane, c0, r0);
}

// ---------------------------------------------------------------------------
// Reductions
// ---------------------------------------------------------------------------
__global__ void k_zero() {
    int t = threadIdx.x;
    if (t < NIMG * 7) ((double*)g_sums)[t] = 0.0;
}

__global__ void k_reduce(const float* __restrict__ tgt) {
    const int n = blockIdx.y;
    const float4* __restrict__ sp = (const float4*)(g_skel + n * HWSZ);
    const float4* __restrict__ sl = (const float4*)(g_skel + (NIMG + n) * HWSZ);
    const float4* __restrict__ pp = (const float4*)(g_p + n * HWSZ);
    const float4* __restrict__ tt = (const float4*)(tgt + n * HWSZ);
    const int n4 = HWSZ / 4;

    double a0 = 0, a1 = 0, a2 = 0, a3 = 0, a4 = 0, a5 = 0, a6 = 0;
    for (int i = blockIdx.x * blockDim.x + threadIdx.x; i < n4;
         i += gridDim.x * blockDim.x) {
        float4 s1 = sp[i], s2 = sl[i], pv = pp[i], tv = tt[i];
        a0 += (double)(s1.x * tv.x + s1.y * tv.y + s1.z * tv.z + s1.w * tv.w);
        a1 += (double)(s1.x + s1.y + s1.z + s1.w);
        a2 += (double)(s2.x * pv.x + s2.y * pv.y + s2.z * pv.z + s2.w * pv.w);
        a3 += (double)(s2.x + s2.y + s2.z + s2.w);
        a4 += (double)(pv.x * tv.x + pv.y * tv.y + pv.z * tv.z + pv.w * tv.w);
        a5 += (double)(pv.x + pv.y + pv.z + pv.w);
        a6 += (double)(tv.x + tv.y + tv.z + tv.w);
    }
#pragma unroll
    for (int o = 16; o > 0; o >>= 1) {
        a0 += __shfl_down_sync(0xffffffffu, a0, o);
        a1 += __shfl_down_sync(0xffffffffu, a1, o);
        a2 += __shfl_down_sync(0xffffffffu, a2, o);
        a3 += __shfl_down_sync(0xffffffffu, a3, o);
        a4 += __shfl_down_sync(0xffffffffu, a4, o);
        a5 += __shfl_down_sync(0xffffffffu, a5, o);
        a6 += __shfl_down_sync(0xffffffffu, a6, o);
    }
    if ((threadIdx.x & 31) == 0) {
        atomicAdd(&g_sums[n][0], a0);
        atomicAdd(&g_sums[n][1], a1);
        atomicAdd(&g_sums[n][2], a2);
        atomicAdd(&g_sums[n][3], a3);
        atomicAdd(&g_sums[n][4], a4);
        atomicAdd(&g_sums[n][5], a5);
        atomicAdd(&g_sums[n][6], a6);
    }
}

__global__ void k_final(float* __restrict__ out, int out_size) {
    if (threadIdx.x == 0 && blockIdx.x == 0) {
        const double smooth = 1.0;
        double cl = 0.0, dice = 0.0;
        for (int n = 0; n < NIMG; n++) {
            double A = g_sums[n][0], B = g_sums[n][1], C = g_sums[n][2],
                   D = g_sums[n][3], E = g_sums[n][4], F = g_sums[n][5],
                   G = g_sums[n][6];
            double tprec = (A + smooth) / (B + smooth);
            double tsens = (C + smooth) / (D + smooth);
            cl += 1.0 - 2.0 * tprec * tsens / (tprec + tsens);
            dice += 1.0 - 2.0 * (E + smooth) / (F + G + smooth);
        }
        cl /= NIMG;
        dice /= NIMG;
        float loss = (float)(0.7 * dice + 0.3 * cl);
        for (int i = 0; i < out_size; i++) out[i] = loss;
    }
}

// ---------------------------------------------------------------------------
extern "C" void kernel_launch(void* const* d_in, const int* in_sizes, int n_in,
                              void* d_out, int out_size) {
    const float* output = (const float*)d_in[0];
    const float* target = (const float*)d_in[1];
    float* out = (float*)d_out;

    k_init<<<1024, 256>>>((const float4*)output, (const float4*)target);

    k_open_init<<<SWEEP_GRID, SWEEP_BLOCK>>>();

    // 50 iterations = 25 fused-2 launches
    for (int j = 0; j < NITER / 2; ++j) {
        k_iter2<<<IT2_GRID, IT2_BLOCK>>>(j & 1);
    }

    k_zero<<<1, 64>>>();
    k_reduce<<<dim3(32, NIMG), 256>>>(target);
    k_final<<<1, 32>>>(out, out_size);
}

// round 12
// speedup vs baseline: 1.1273x; 1.1273x over previous
#include <cuda_runtime.h>
#include <cuda_fp16.h>
#include <math.h>

#define WW 512
#define HH 512
#define NIMG 8
#define HWSZ (HH * WW)
#define NPLANES 16            // 2 streams (p, target) x 8 samples
#define TOTALSZ (NPLANES * HWSZ)
#define NITER 50

#define STRIPS 5              // 5 strips x 120 output cols (lanes 1..30 of 4-col lanes)
#define CHUNK_ROWS 16
#define CHUNKS 32             // 512 / 16
#define WARPS_TOTAL (STRIPS * CHUNKS * NPLANES)   // 2560

#define SWEEP_BLOCK 256
#define SWEEP_GRID (WARPS_TOTAL / (SWEEP_BLOCK / 32))  // 320

#define IT2_BLOCK 128
#define IT2_GRID (WARPS_TOTAL / (IT2_BLOCK / 32))      // 640

// Static scratch (no allocations allowed in kernel_launch)
__device__ float  g_p[NIMG * HWSZ];    // sigmoid(output) fp32, for the Dice-side reduction
__device__ __half g_imgA[TOTALSZ];     // ping (fp16)
__device__ __half g_imgB[TOTALSZ];     // pong (fp16)
__device__ __half g_skel[TOTALSZ];     // skeleton accumulators (fp16)
__device__ double g_sums[NIMG][7];     // per-sample reduction accumulators

// ---------------------------------------------------------------------------
// fp16x4 helpers: one lane owns 4 adjacent columns as {lo=(c0,c1), hi=(c2,c3)}
// ---------------------------------------------------------------------------
struct __align__(8) H4 { __half2 lo, hi; };

__device__ __forceinline__ __half h_inf()  { return __ushort_as_half((unsigned short)0x7C00); }
__device__ __forceinline__ __half h_ninf() { return __ushort_as_half((unsigned short)0xFC00); }
__device__ __forceinline__ H4 h4fill(__half v) { __half2 p = __half2half2(v); H4 r; r.lo = p; r.hi = p; return r; }
__device__ __forceinline__ H4 h4_inf()  { return h4fill(h_inf()); }
__device__ __forceinline__ H4 h4_ninf() { return h4fill(h_ninf()); }
__device__ __forceinline__ H4 h4_zero() { return h4fill(__ushort_as_half(0)); }

__device__ __forceinline__ H4 min_h(H4 a, H4 b) { H4 r; r.lo = __hmin2(a.lo, b.lo); r.hi = __hmin2(a.hi, b.hi); return r; }
__device__ __forceinline__ H4 max_h(H4 a, H4 b) { H4 r; r.lo = __hmax2(a.lo, b.lo); r.hi = __hmax2(a.hi, b.hi); return r; }
__device__ __forceinline__ H4 vmin3h(H4 a, H4 b, H4 c) { return min_h(min_h(a, b), c); }
__device__ __forceinline__ H4 vmax3h(H4 a, H4 b, H4 c) { return max_h(max_h(a, b), c); }

// horizontal 3-tap min across the warp-wide row
__device__ __forceinline__ H4 hmin3h(H4 v, int lane) {
    __half2 fl = __shfl_up_sync(0xffffffffu, v.hi, 1);
    __half2 fr = __shfl_down_sync(0xffffffffu, v.lo, 1);
    __half L = (lane == 0)  ? h_inf() : __high2half(fl);
    __half R = (lane == 31) ? h_inf() : __low2half(fr);
    __half2 La = __halves2half2(L, __low2half(v.lo));                   // {L, a}
    __half2 bc = __halves2half2(__high2half(v.lo), __low2half(v.hi));   // {b, c}
    __half2 dR = __halves2half2(__high2half(v.hi), R);                  // {d, R}
    H4 o;
    o.lo = __hmin2(__hmin2(La, v.lo), bc);   // {min(L,a,b), min(a,b,c)}
    o.hi = __hmin2(__hmin2(bc, v.hi), dR);   // {min(b,c,d), min(c,d,R)}
    return o;
}
__device__ __forceinline__ H4 hmax3h(H4 v, int lane) {
    __half2 fl = __shfl_up_sync(0xffffffffu, v.hi, 1);
    __half2 fr = __shfl_down_sync(0xffffffffu, v.lo, 1);
    __half L = (lane == 0)  ? h_ninf() : __high2half(fl);
    __half R = (lane == 31) ? h_ninf() : __low2half(fr);
    __half2 La = __halves2half2(L, __low2half(v.lo));
    __half2 bc = __halves2half2(__high2half(v.lo), __low2half(v.hi));
    __half2 dR = __halves2half2(__high2half(v.hi), R);
    H4 o;
    o.lo = __hmax2(__hmax2(La, v.lo), bc);
    o.hi = __hmax2(__hmax2(bc, v.hi), dR);
    return o;
}
__device__ __forceinline__ H4 relu_subh(H4 a, H4 b) {
    __half2 z = __half2half2(__ushort_as_half(0));
    H4 r;
    r.lo = __hmax2(__hsub2(a.lo, b.lo), z);
    r.hi = __hmax2(__hsub2(a.hi, b.hi), z);
    return r;
}
__device__ __forceinline__ H4 selneg(H4 v, bool ok) { return ok ? v : h4_ninf(); }
// s += relu(d - s*d)
__device__ __forceinline__ void skel_updh(H4& s, H4 d) {
    s.lo = __hadd2(s.lo, __hfma2_relu(__hneg2(s.lo), d.lo, d.lo));
    s.hi = __hadd2(s.hi, __hfma2_relu(__hneg2(s.hi), d.hi, d.hi));
}

// ---------------------------------------------------------------------------
// Init: p = sigmoid(output); g_p fp32; imgA[stream0]=half(p), imgA[stream1]=half(target)
// ---------------------------------------------------------------------------
__global__ void k_init(const float4* __restrict__ out, const float4* __restrict__ tgt) {
    int i = blockIdx.x * blockDim.x + threadIdx.x;
    int stride = gridDim.x * blockDim.x;
    float4* gp = (float4*)g_p;
    H4* ga = (H4*)g_imgA;
    H4* gb = (H4*)(g_imgA + NIMG * HWSZ);
    const int n4 = NIMG * HWSZ / 4;
    for (; i < n4; i += stride) {
        float4 o = out[i];
        float4 v;
        v.x = 1.0f / (1.0f + expf(-o.x));
        v.y = 1.0f / (1.0f + expf(-o.y));
        v.z = 1.0f / (1.0f + expf(-o.z));
        v.w = 1.0f / (1.0f + expf(-o.w));
        gp[i] = v;
        H4 hv; hv.lo = __floats2half2_rn(v.x, v.y); hv.hi = __floats2half2_rn(v.z, v.w);
        ga[i] = hv;
        float4 t = tgt[i];
        H4 ht; ht.lo = __floats2half2_rn(t.x, t.y); ht.hi = __floats2half2_rn(t.z, t.w);
        gb[i] = ht;
    }
}

// ---------------------------------------------------------------------------
// Warp-sweep open-init:  skel = relu(img - dilate(erode(img)))   (fp16)
// ---------------------------------------------------------------------------
__global__ void __launch_bounds__(SWEEP_BLOCK, 3) k_open_init() {
    const int lane = threadIdx.x & 31;
    const int gw = (blockIdx.x * SWEEP_BLOCK + threadIdx.x) >> 5;
    const int strip = gw % STRIPS;
    const int t = gw / STRIPS;
    const int chunk = t & (CHUNKS - 1);
    const int z = t >> 5;

    const __half* __restrict__ src = g_imgA + z * HWSZ;
    __half* __restrict__ skel = g_skel + z * HWSZ;

    const int c0 = strip * 120 - 4 + 4 * lane;
    const bool colok = (c0 >= 0) && (c0 < WW);
    const bool stok = (lane >= 1) && (lane <= 30) && (c0 < WW);
    const int r0 = chunk * CHUNK_ROWS;
    const int ylim = r0 + 2;

    int y = r0 - 2;
    const __half* srcp = src + y * WW + c0;
    __half* const skb = skel + c0;

    H4 ia = h4_inf(), ib = h4_inf(), ic;
    H4 ha = h4_ninf(), hb = h4_ninf(), hc;

#define OPEN_STEP(IA, IB, IC, HA, HB, HC)                                      \
    {                                                                          \
        bool ldok = colok && ((unsigned)y < (unsigned)HH);                     \
        IC = ldok ? *(const H4*)srcp : h4_inf();                               \
        H4 e1_ = min_h(vmin3h(IA, IB, IC), hmin3h(IB, lane));                  \
        if (!colok || (unsigned)(y - 1) >= (unsigned)HH) e1_ = h4_ninf();      \
        HC = hmax3h(e1_, lane);                                                \
        if (y >= ylim) {                                                       \
            H4 d_ = vmax3h(HA, HB, HC);                                        \
            if (stok) {                                                        \
                H4 o_ = relu_subh(IA, d_);                                     \
                *(H4*)(skb + (y - 2) * WW) = o_;                               \
            }                                                                  \
        }                                                                      \
        ++y;                                                                   \
        srcp += WW;                                                            \
    }

#pragma unroll 1
    for (int k = 0; k < 6; ++k) {
        OPEN_STEP(ia, ib, ic, ha, hb, hc);
        OPEN_STEP(ib, ic, ia, hb, hc, ha);
        OPEN_STEP(ic, ia, ib, hc, ha, hb);
    }
    OPEN_STEP(ia, ib, ic, ha, hb, hc);
    OPEN_STEP(ib, ic, ia, hb, hc, ha);
#undef OPEN_STEP
}

// ---------------------------------------------------------------------------
// Fused TWO skeleton iterations (R7 structure), fp16 lanes (4 cols/lane):
//   E1 = erode(img); E2 = erode(E1) -> new img; E3 = erode(E2)
//   delta1 = relu(E1 - dilate(E2)); delta2 = relu(E2 - dilate(E3))
//   skel row: one load, both updates in-register, one store.
// Vertical/horizontal halo 4; vertical +inf masks on E-rings are redundant
// under min; only the -inf masks at the two hmax feeds remain.
// ---------------------------------------------------------------------------
__global__ void __launch_bounds__(IT2_BLOCK, 6) k_iter2(int flip) {
    const int lane = threadIdx.x & 31;
    const int gw = (blockIdx.x * IT2_BLOCK + threadIdx.x) >> 5;
    const int strip = gw % STRIPS;
    const int t = gw / STRIPS;
    const int chunk = t & (CHUNKS - 1);
    const int z = t >> 5;

    const __half* __restrict__ src = (flip ? g_imgB : g_imgA) + z * HWSZ;
    __half* __restrict__ dst = (flip ? g_imgA : g_imgB) + z * HWSZ;
    __half* __restrict__ skel = g_skel + z * HWSZ;

    const int c0 = strip * 120 - 4 + 4 * lane;
    const bool colok = (c0 >= 0) && (c0 < WW);
    const bool stok = (lane >= 1) && (lane <= 30) && (c0 < WW);
    const int r0 = chunk * CHUNK_ROWS;
    const int yD1 = r0 + 3;    // first step producing delta1 (row y-3)
    const int yOUT = r0 + 4;   // first step producing output (row y-4)

    int y = r0 - 4;
    H4 pf;
    {
        bool ldok = colok && ((unsigned)y < (unsigned)HH);
        pf = ldok ? *(const H4*)(src + y * WW + c0) : h4_inf();
    }
    const __half* srcp = src + (y + 1) * WW + c0;
    __half* const skb = skel + c0;
    __half* const dsb = dst + c0;

    H4 ia = h4_inf(), ib = h4_inf(), ic;        // I ring
    H4 ea = h4_inf(), eb = h4_inf(), ec;        // E1 ring
    H4 fa = h4_inf(), fb = h4_inf(), fc;        // E2 ring
    H4 ha = h4_ninf(), hb = h4_ninf(), hc;      // H = hmax(E2)
    H4 ba = h4_ninf(), bb = h4_ninf(), bc;      // Hb = hmax(E3)
    H4 dprev = h4_zero();                       // delta1[y-4]
    H4 spf = h4_zero();                         // skel prefetch

#define STEP2(IA, IB, IC, EA, EB, EC, FA, FB, FC, HA, HB, HC, BA, BB, BC)      \
    {                                                                          \
        H4 icur = pf;                                                          \
        {                                                                      \
            bool ldok = colok && ((unsigned)(y + 1) < (unsigned)HH);           \
            pf = ldok ? *(const H4*)srcp : h4_inf();                           \
            srcp += WW;                                                        \
        }                                                                      \
        IC = icur;                                                             \
        EC = min_h(vmin3h(IA, IB, IC), hmin3h(IB, lane));    /* E1[y-1] */     \
        FC = min_h(vmin3h(EA, EB, EC), hmin3h(EB, lane));    /* E2[y-2] */     \
        HC = hmax3h(selneg(FC, colok && (unsigned)(y - 2) < (unsigned)HH),     \
                    lane);                                                     \
        H4 e3_ = min_h(vmin3h(FA, FB, FC), hmin3h(FB, lane)); /* E3[y-3] */    \
        BC = hmax3h(selneg(e3_, colok && (unsigned)(y - 3) < (unsigned)HH),    \
                    lane);                                                     \
        if (y >= yOUT) {                                     /* row y-4 */     \
            H4 D2 = vmax3h(BA, BB, BC);                                        \
            if (stok) {                                                        \
                H4 d2 = relu_subh(FA, D2);                   /* E2[y-4] */     \
                H4 s = spf;                                                    \
                skel_updh(s, dprev);                                           \
                skel_updh(s, d2);                                              \
                *(H4*)(skb + (y - 4) * WW) = s;                                \
                *(H4*)(dsb + (y - 4) * WW) = FA;                               \
            }                                                                  \
        }                                                                      \
        if (y >= yD1) {                                      /* delta1 y-3 */  \
            H4 D1 = vmax3h(HA, HB, HC);                                        \
            dprev = relu_subh(EA, D1);                       /* E1[y-3] */     \
            if (stok && (unsigned)(y - 3) < (unsigned)HH)                      \
                spf = *(const H4*)(skb + (y - 3) * WW);                        \
        }                                                                      \
        ++y;                                                                   \
    }

    // 24 steps = 8 groups of 3 (ring rotation by argument permutation)
#pragma unroll 1
    for (int k = 0; k < 8; ++k) {
        STEP2(ia, ib, ic, ea, eb, ec, fa, fb, fc, ha, hb, hc, ba, bb, bc);
        STEP2(ib, ic, ia, eb, ec, ea, fb, fc, fa, hb, hc, ha, bb, bc, ba);
        STEP2(ic, ia, ib, ec, ea, eb, fc, fa, fb, hc, ha, hb, bc, ba, bb);
    }
#undef STEP2
}

// ---------------------------------------------------------------------------
// Reductions
// ---------------------------------------------------------------------------
__global__ void k_zero() {
    int t = threadIdx.x;
    if (t < NIMG * 7) ((double*)g_sums)[t] = 0.0;
}

__global__ void k_reduce(const float* __restrict__ tgt) {
    const int n = blockIdx.y;
    const H4* __restrict__ sp = (const H4*)(g_skel + n * HWSZ);
    const H4* __restrict__ sl = (const H4*)(g_skel + (NIMG + n) * HWSZ);
    const float4* __restrict__ pp = (const float4*)(g_p + n * HWSZ);
    const float4* __restrict__ tt = (const float4*)(tgt + n * HWSZ);
    const int n4 = HWSZ / 4;

    double a0 = 0, a1 = 0, a2 = 0, a3 = 0, a4 = 0, a5 = 0, a6 = 0;
    for (int i = blockIdx.x * blockDim.x + threadIdx.x; i < n4;
         i += gridDim.x * blockDim.x) {
        H4 s1h = sp[i], s2h = sl[i];
        float2 s1lo = __half22float2(s1h.lo), s1hi = __half22float2(s1h.hi);
        float2 s2lo = __half22float2(s2h.lo), s2hi = __half22float2(s2h.hi);
        float4 pv = pp[i], tv = tt[i];
        a0 += (double)(s1lo.x * tv.x + s1lo.y * tv.y + s1hi.x * tv.z + s1hi.y * tv.w);
        a1 += (double)(s1lo.x + s1lo.y + s1hi.x + s1hi.y);
        a2 += (double)(s2lo.x * pv.x + s2lo.y * pv.y + s2hi.x * pv.z + s2hi.y * pv.w);
        a3 += (double)(s2lo.x + s2lo.y + s2hi.x + s2hi.y);
        a4 += (double)(pv.x * tv.x + pv.y * tv.y + pv.z * tv.z + pv.w * tv.w);
        a5 += (double)(pv.x + pv.y + pv.z + pv.w);
        a6 += (double)(tv.x + tv.y + tv.z + tv.w);
    }
#pragma unroll
    for (int o = 16; o > 0; o >>= 1) {
        a0 += __shfl_down_sync(0xffffffffu, a0, o);
        a1 += __shfl_down_sync(0xffffffffu, a1, o);
        a2 += __shfl_down_sync(0xffffffffu, a2, o);
        a3 += __shfl_down_sync(0xffffffffu, a3, o);
        a4 += __shfl_down_sync(0xffffffffu, a4, o);
        a5 += __shfl_down_sync(0xffffffffu, a5, o);
        a6 += __shfl_down_sync(0xffffffffu, a6, o);
    }
    if ((threadIdx.x & 31) == 0) {
        atomicAdd(&g_sums[n][0], a0);
        atomicAdd(&g_sums[n][1], a1);
        atomicAdd(&g_sums[n][2], a2);
        atomicAdd(&g_sums[n][3], a3);
        atomicAdd(&g_sums[n][4], a4);
        atomicAdd(&g_sums[n][5], a5);
        atomicAdd(&g_sums[n][6], a6);
    }
}

__global__ void k_final(float* __restrict__ out, int out_size) {
    if (threadIdx.x == 0 && blockIdx.x == 0) {
        const double smooth = 1.0;
        double cl = 0.0, dice = 0.0;
        for (int n = 0; n < NIMG; n++) {
            double A = g_sums[n][0], B = g_sums[n][1], C = g_sums[n][2],
                   D = g_sums[n][3], E = g_sums[n][4], F = g_sums[n][5],
                   G = g_sums[n][6];
            double tprec = (A + smooth) / (B + smooth);
            double tsens = (C + smooth) / (D + smooth);
            cl += 1.0 - 2.0 * tprec * tsens / (tprec + tsens);
            dice += 1.0 - 2.0 * (E + smooth) / (F + G + smooth);
        }
        cl /= NIMG;
        dice /= NIMG;
        float loss = (float)(0.7 * dice + 0.3 * cl);
        for (int i = 0; i < out_size; i++) out[i] = loss;
    }
}

// ---------------------------------------------------------------------------
extern "C" void kernel_launch(void* const* d_in, const int* in_sizes, int n_in,
                              void* d_out, int out_size) {
    const float* output = (const float*)d_in[0];
    const float* target = (const float*)d_in[1];
    float* out = (float*)d_out;

    k_init<<<1024, 256>>>((const float4*)output, (const float4*)target);

    k_open_init<<<SWEEP_GRID, SWEEP_BLOCK>>>();

    // 50 iterations = 25 fused-2 launches
    for (int j = 0; j < NITER / 2; ++j) {
        k_iter2<<<IT2_GRID, IT2_BLOCK>>>(j & 1);
    }

    k_zero<<<1, 64>>>();
    k_reduce<<<dim3(32, NIMG), 256>>>(target);
    k_final<<<1, 32>>>(out, out_size);
}